// round 7
// baseline (speedup 1.0000x reference)
#include <cuda_runtime.h>
#include <cuda_fp16.h>
#include <cstdint>

#define Bsz 4
#define Cch 256
#define Hh  64
#define Ww  64
#define Oo  256
#define Kt  9
#define Md  (Bsz*Hh*Ww)   // 16384
#define Kd  (Cch*Kt)      // 2304

// ---------------- scratch ----------------
__device__ __half g_nhwc16[(size_t)Bsz*Hh*Ww*Cch];
__device__ float g_off[(size_t)Bsz*18*Hh*Ww];
__device__ __half g_A[(size_t)Md*Kd];
__device__ __half g_B[(size_t)Oo*Kd];
__device__ float g_bias2[Oo];

// ---------------- helpers ----------------
__device__ __forceinline__ uint32_t smem_u32(const void* p) {
    uint32_t a;
    asm("{ .reg .u64 t; cvta.to.shared.u64 t, %1; cvt.u32.u64 %0, t; }" : "=r"(a) : "l"(p));
    return a;
}
__device__ __forceinline__ void cpa16(uint32_t s, const void* g) {
    asm volatile("cp.async.cg.shared.global [%0], [%1], 16;" :: "r"(s), "l"(g));
}
#define LDMX4(r, addr) \
    asm volatile("ldmatrix.sync.aligned.m8n8.x4.shared.b16 {%0,%1,%2,%3}, [%4];" \
        : "=r"((r)[0]), "=r"((r)[1]), "=r"((r)[2]), "=r"((r)[3]) : "r"(addr))
#define MMA16816(d, a, b0, b1) \
    asm volatile("mma.sync.aligned.m16n8k16.row.col.f32.f16.f16.f32 " \
        "{%0,%1,%2,%3}, {%4,%5,%6,%7}, {%8,%9}, {%0,%1,%2,%3};" \
        : "+f"((d)[0]), "+f"((d)[1]), "+f"((d)[2]), "+f"((d)[3]) \
        : "r"((a)[0]), "r"((a)[1]), "r"((a)[2]), "r"((a)[3]), "r"(b0), "r"(b1))

// ---------------- 1) NCHW -> NHWC(fp16) transpose + weight prep (fused) ----------------
__global__ void k_transpose_prep(const float* __restrict__ in,
                                 const float* __restrict__ w,
                                 const float* __restrict__ bias,
                                 const float* __restrict__ gamma,
                                 const float* __restrict__ beta,
                                 const float* __restrict__ mean,
                                 const float* __restrict__ var) {
    if (blockIdx.y == 8) {
        int o = blockIdx.z;
        int tid = threadIdx.y * 32 + threadIdx.x;
        float inv = gamma[o] * rsqrtf(var[o] + 1e-5f);
        int kd0 = blockIdx.x * (Kd/2);
        for (int i = tid; i < Kd/2; i += 256) {
            int kd = kd0 + i;
            int tap = kd >> 8, c = kd & 255;
            g_B[(size_t)o*Kd + kd] = __float2half_rn(w[((size_t)(o*Cch + c))*9 + tap] * inv);
        }
        if (tid == 0 && blockIdx.x == 0)
            g_bias2[o] = bias[o]*inv + beta[o] - mean[o]*inv;
        return;
    }
    __shared__ float t[32][33];
    int x0 = blockIdx.x * 32;
    int c0 = blockIdx.y * 32;
    int bh = blockIdx.z;
    int b = bh >> 6, y = bh & 63;
    #pragma unroll
    for (int i = threadIdx.y; i < 32; i += 8)
        t[i][threadIdx.x] = in[(((size_t)(b*Cch + c0 + i)*Hh + y)*Ww) + x0 + threadIdx.x];
    __syncthreads();
    #pragma unroll
    for (int i = threadIdx.y; i < 32; i += 8)
        g_nhwc16[(((size_t)(b*Hh + y)*Ww + x0 + i) << 8) + c0 + threadIdx.x] =
            __float2half_rn(t[threadIdx.x][i]);
}

// ---------------- 2) offset conv (fp32) ----------------
#define OC_CH 16
__global__ __launch_bounds__(256) void k_offset_conv(const float* __restrict__ in,
                                                     const float* __restrict__ w_off,
                                                     const float* __restrict__ b_off) {
    int bid = blockIdx.x;
    int b = bid >> 6, y = bid & 63;
    int tid = threadIdx.x;
    int x  = tid & 63;
    int jj = tid >> 6;
    __shared__ float sin_[3][OC_CH][66];
    __shared__ float ws[18][OC_CH][9];
    float acc[5] = {0.f, 0.f, 0.f, 0.f, 0.f};

    for (int c0 = 0; c0 < Cch; c0 += OC_CH) {
        for (int idx = tid; idx < 3*OC_CH*66; idx += 256) {
            int r  = idx / (OC_CH*66);
            int rem = idx - r*(OC_CH*66);
            int cc = rem / 66;
            int xx = rem - cc*66;
            int gy = y - 1 + r;
            int gx = xx - 1;
            float v = 0.f;
            if ((unsigned)gy < 64u && (unsigned)gx < 64u)
                v = in[(((size_t)(b*Cch + c0 + cc)*Hh + gy)*Ww) + gx];
            sin_[r][cc][xx] = v;
        }
        for (int idx = tid; idx < 18*OC_CH*9; idx += 256) {
            int j  = idx / (OC_CH*9);
            int rem = idx - j*(OC_CH*9);
            int cc = rem / 9;
            int p  = rem - cc*9;
            ws[j][cc][p] = w_off[((size_t)(j*Cch + c0 + cc))*9 + p];
        }
        __syncthreads();
        for (int cc = 0; cc < OC_CH; cc++) {
            #pragma unroll
            for (int i = 0; i < 3; i++) {
                #pragma unroll
                for (int jx = 0; jx < 3; jx++) {
                    float v = sin_[i][cc][x + jx];
                    int p = i*3 + jx;
                    #pragma unroll
                    for (int t = 0; t < 5; t++) {
                        int j = jj + (t << 2);
                        if (j < 18) acc[t] += v * ws[j][cc][p];
                    }
                }
            }
        }
        __syncthreads();
    }
    #pragma unroll
    for (int t = 0; t < 5; t++) {
        int j = jj + (t << 2);
        if (j < 18)
            g_off[(((size_t)(b*18 + j)*Hh + y)*Ww) + x] = acc[t] + b_off[j];
    }
}

// ---------------- 3) bilinear sample (fp16 gather) -> fp16 im2col ----------------
__global__ __launch_bounds__(256) void k_sample() {
    int m = blockIdx.x * 4 + (threadIdx.x >> 6);
    int b = m >> 12, y = (m >> 6) & 63, x = m & 63;
    int c = (threadIdx.x & 63) * 4;

    #pragma unroll
    for (int k = 0; k < Kt; k++) {
        float dy = g_off[(((size_t)(b*18 + 2*k    )*Hh + y)*Ww) + x];
        float dx = g_off[(((size_t)(b*18 + 2*k + 1)*Hh + y)*Ww) + x];
        float py = (float)(y - 1 + (k/3)) + dy;
        float px = (float)(x - 1 + (k%3)) + dx;
        float y0f = floorf(py), x0f = floorf(px);
        float ly = py - y0f, lx = px - x0f;
        int y0 = (int)y0f, x0i = (int)x0f;
        int y1 = y0 + 1,  x1 = x0i + 1;
        float vy0 = (y0  >= 0 && y0  < 64) ? 1.f : 0.f;
        float vy1 = (y1  >= 0 && y1  < 64) ? 1.f : 0.f;
        float vx0 = (x0i >= 0 && x0i < 64) ? 1.f : 0.f;
        float vx1 = (x1  >= 0 && x1  < 64) ? 1.f : 0.f;
        float w00 = (1.f-ly)*(1.f-lx)*vy0*vx0;
        float w01 = (1.f-ly)*lx      *vy0*vx1;
        float w10 = ly      *(1.f-lx)*vy1*vx0;
        float w11 = ly      *lx      *vy1*vx1;
        int y0c = min(max(y0, 0), 63), y1c = min(max(y1, 0), 63);
        int x0c = min(max(x0i,0), 63), x1c = min(max(x1, 0), 63);
        const __half* p00 = g_nhwc16 + (((size_t)(b*Hh + y0c)*Ww + x0c) << 8) + c;
        const __half* p01 = g_nhwc16 + (((size_t)(b*Hh + y0c)*Ww + x1c) << 8) + c;
        const __half* p10 = g_nhwc16 + (((size_t)(b*Hh + y1c)*Ww + x0c) << 8) + c;
        const __half* p11 = g_nhwc16 + (((size_t)(b*Hh + y1c)*Ww + x1c) << 8) + c;
        uint2 u00 = *(const uint2*)p00;
        uint2 u01 = *(const uint2*)p01;
        uint2 u10 = *(const uint2*)p10;
        uint2 u11 = *(const uint2*)p11;
        float2 f00a = __half22float2(*(__half2*)&u00.x), f00b = __half22float2(*(__half2*)&u00.y);
        float2 f01a = __half22float2(*(__half2*)&u01.x), f01b = __half22float2(*(__half2*)&u01.y);
        float2 f10a = __half22float2(*(__half2*)&u10.x), f10b = __half22float2(*(__half2*)&u10.y);
        float2 f11a = __half22float2(*(__half2*)&u11.x), f11b = __half22float2(*(__half2*)&u11.y);
        float4 r;
        r.x = w00*f00a.x + w01*f01a.x + w10*f10a.x + w11*f11a.x;
        r.y = w00*f00a.y + w01*f01a.y + w10*f10a.y + w11*f11a.y;
        r.z = w00*f00b.x + w01*f01b.x + w10*f10b.x + w11*f11b.x;
        r.w = w00*f00b.y + w01*f01b.y + w10*f10b.y + w11*f11b.y;

        __half2 h01 = __halves2half2(__float2half_rn(r.x), __float2half_rn(r.y));
        __half2 h23 = __halves2half2(__float2half_rn(r.z), __float2half_rn(r.w));
        uint2 pk;
        pk.x = *(uint32_t*)&h01;
        pk.y = *(uint32_t*)&h23;
        *(uint2*)(g_A + (size_t)m*Kd + k*Cch + c) = pk;
    }
}

// ---------------- 4) fp16 mma.sync GEMM, 512 threads, 4-stage pipe ----------------
#define KC 32
#define NCH (Kd/KC)          // 72
#define APL 10240            // A plane (128 rows x 80B)
#define BPL 20480            // B plane (256 rows x 80B)
#define BOFF APL
#define STG (APL + BPL)      // 30720 per stage
#define NSTG 4

__global__ __launch_bounds__(512, 1) void k_gemm_mma(float* __restrict__ out) {
    extern __shared__ char dsm[];
    const uint32_t sbase = smem_u32(dsm);
    const int tid = threadIdx.x, lid = tid & 31, wid = tid >> 5;
    const int warpM = wid & 1, warpN = wid >> 1;   // 2 x 8 -> warp tile 64x32
    const int m0 = blockIdx.x * 128;

    float acc[4][4][4];
    #pragma unroll
    for (int mt = 0; mt < 4; mt++)
        #pragma unroll
        for (int nt = 0; nt < 4; nt++)
            #pragma unroll
            for (int j = 0; j < 4; j++) acc[mt][nt][j] = 0.f;

    const uint32_t a_off = (uint32_t)((warpM*64 + (lid & 15)) * 80 + (lid >> 4) * 16);
    const uint32_t bm_off = (uint32_t)((warpN*32 + (lid & 7) + ((lid >> 4) & 1)*8) * 80
                                       + ((lid >> 3) & 1) * 16);

    auto load = [&](int c, int p) {
        uint32_t sb = sbase + p * STG;
        size_t kOff = (size_t)c * KC;
        // A: 512 ops (128 rows x 4 x 16B) -> exactly one per thread
        {
            int rr = tid >> 2;
            int j  = tid & 3;
            cpa16(sb + rr*80 + j*16, g_A + (size_t)(m0 + rr)*Kd + kOff + j*8);
        }
        // B: 1024 ops (256 rows x 4 x 16B)
        #pragma unroll
        for (int i = 0; i < 2; i++) {
            int idx = tid + i*512;
            int rr = idx >> 2;
            int j  = idx & 3;
            cpa16(sb + BOFF + rr*80 + j*16, g_B + (size_t)rr*Kd + kOff + j*8);
        }
        asm volatile("cp.async.commit_group;");
    };

    load(0, 0);
    load(1, 1);
    load(2, 2);

    for (int c = 0; c < NCH; c++) {
        int p = c & 3;
        if (c + 3 < NCH) {
            load(c + 3, (c + 3) & 3);
            asm volatile("cp.async.wait_group 3;" ::: "memory");
        } else if (c + 2 < NCH) {
            asm volatile("cp.async.wait_group 2;" ::: "memory");
        } else if (c + 1 < NCH) {
            asm volatile("cp.async.wait_group 1;" ::: "memory");
        } else {
            asm volatile("cp.async.wait_group 0;" ::: "memory");
        }
        __syncthreads();

        uint32_t sb = sbase + p * STG;
        #pragma unroll
        for (int kh = 0; kh < 2; kh++) {
            uint32_t ah[4][4];
            #pragma unroll
            for (int mt = 0; mt < 4; mt++)
                LDMX4(ah[mt], sb + a_off + mt*(16*80) + kh*32);
            #pragma unroll
            for (int tp = 0; tp < 2; tp++) {
                uint32_t bb[4];
                LDMX4(bb, sb + BOFF + bm_off + tp*(16*80) + kh*32);
                #pragma unroll
                for (int q = 0; q < 2; q++) {
                    int nt = tp*2 + q;
                    #pragma unroll
                    for (int mt = 0; mt < 4; mt++)
                        MMA16816(acc[mt][nt], ah[mt], bb[2*q], bb[2*q+1]);
                }
            }
        }
        __syncthreads();
    }

    // epilogue: bias + relu, NCHW stores
    #pragma unroll
    for (int mt = 0; mt < 4; mt++) {
        int mA = m0 + warpM*64 + mt*16 + (lid >> 2);
        int mB = mA + 8;
        int bA = mA >> 12, bB = mB >> 12;
        int pA = mA & 4095, pB = mB & 4095;
        #pragma unroll
        for (int nt = 0; nt < 4; nt++) {
            int o = warpN*32 + nt*8 + (lid & 3)*2;
            float bv0 = g_bias2[o], bv1 = g_bias2[o + 1];
            float* d = acc[mt][nt];
            out[((size_t)bA << 20) + ((size_t)o << 12)     + pA] = fmaxf(d[0] + bv0, 0.f);
            out[((size_t)bA << 20) + ((size_t)(o+1) << 12) + pA] = fmaxf(d[1] + bv1, 0.f);
            out[((size_t)bB << 20) + ((size_t)o << 12)     + pB] = fmaxf(d[2] + bv0, 0.f);
            out[((size_t)bB << 20) + ((size_t)(o+1) << 12) + pB] = fmaxf(d[3] + bv1, 0.f);
        }
    }
}

// ---------------- launch ----------------
extern "C" void kernel_launch(void* const* d_in, const int* in_sizes, int n_in,
                              void* d_out, int out_size) {
    const float* input  = (const float*)d_in[0];
    const float* w_off  = (const float*)d_in[1];
    const float* b_off  = (const float*)d_in[2];
    const float* weight = (const float*)d_in[3];
    const float* bias   = (const float*)d_in[4];
    const float* gamma  = (const float*)d_in[5];
    const float* beta   = (const float*)d_in[6];
    const float* mean   = (const float*)d_in[7];
    const float* var    = (const float*)d_in[8];
    float* out = (float*)d_out;

    cudaFuncSetAttribute(k_gemm_mma, cudaFuncAttributeMaxDynamicSharedMemorySize, NSTG*STG);

    k_transpose_prep<<<dim3(2, 9, Bsz*Hh), dim3(32, 8)>>>(input, weight, bias, gamma, beta, mean, var);
    k_offset_conv<<<Bsz*Hh, 256>>>(input, w_off, b_off);
    k_sample<<<Md/4, 256>>>();
    k_gemm_mma<<<Md/128, 512, NSTG*STG>>>(out);
}

// round 8
// speedup vs baseline: 1.7323x; 1.7323x over previous
#include <cuda_runtime.h>
#include <cuda_fp16.h>
#include <cstdint>

#define Bsz 4
#define Cch 256
#define Hh  64
#define Ww  64
#define Oo  256
#define Kt  9
#define Md  (Bsz*Hh*Ww)   // 16384
#define Kd  (Cch*Kt)      // 2304

// ---------------- scratch ----------------
__device__ __half g_nhwcH[(size_t)Bsz*Hh*Ww*Cch];   // fp16 hi plane
__device__ __half g_nhwcL[(size_t)Bsz*Hh*Ww*Cch];   // fp16 residual plane
__device__ float g_off[(size_t)Bsz*18*Hh*Ww];
__device__ __half g_A[(size_t)Md*Kd];
__device__ __half g_B[(size_t)Oo*Kd];
__device__ __half g_Boff[(size_t)32*Kd];            // offset-conv weights, rows 18..31 zero
__device__ float g_bias2[Oo];

// ---------------- helpers ----------------
__device__ __forceinline__ uint32_t smem_u32(const void* p) {
    uint32_t a;
    asm("{ .reg .u64 t; cvta.to.shared.u64 t, %1; cvt.u32.u64 %0, t; }" : "=r"(a) : "l"(p));
    return a;
}
__device__ __forceinline__ void cpa16(uint32_t s, const void* g) {
    asm volatile("cp.async.cg.shared.global [%0], [%1], 16;" :: "r"(s), "l"(g));
}
__device__ __forceinline__ void cpa16z(uint32_t s, const void* g, int valid) {
    asm volatile("cp.async.cg.shared.global [%0], [%1], 16, %2;"
                 :: "r"(s), "l"(g), "r"(valid ? 16 : 0));
}
#define LDMX4(r, addr) \
    asm volatile("ldmatrix.sync.aligned.m8n8.x4.shared.b16 {%0,%1,%2,%3}, [%4];" \
        : "=r"((r)[0]), "=r"((r)[1]), "=r"((r)[2]), "=r"((r)[3]) : "r"(addr))
#define MMA16816(d, a, b0, b1) \
    asm volatile("mma.sync.aligned.m16n8k16.row.col.f32.f16.f16.f32 " \
        "{%0,%1,%2,%3}, {%4,%5,%6,%7}, {%8,%9}, {%0,%1,%2,%3};" \
        : "+f"((d)[0]), "+f"((d)[1]), "+f"((d)[2]), "+f"((d)[3]) \
        : "r"((a)[0]), "r"((a)[1]), "r"((a)[2]), "r"((a)[3]), "r"(b0), "r"(b1))

// ---------------- 1) transpose to fp16 hi/lo NHWC + weight prep ----------------
__global__ void k_transpose_prep(const float* __restrict__ in,
                                 const float* __restrict__ w,
                                 const float* __restrict__ w_off,
                                 const float* __restrict__ bias,
                                 const float* __restrict__ gamma,
                                 const float* __restrict__ beta,
                                 const float* __restrict__ mean,
                                 const float* __restrict__ var) {
    if (blockIdx.y == 8) {
        int o = blockIdx.z;
        int tid = threadIdx.y * 32 + threadIdx.x;
        float inv = gamma[o] * rsqrtf(var[o] + 1e-5f);
        int kd0 = blockIdx.x * (Kd/2);
        for (int i = tid; i < Kd/2; i += 256) {
            int kd = kd0 + i;
            int tap = kd >> 8, c = kd & 255;
            g_B[(size_t)o*Kd + kd] = __float2half_rn(w[((size_t)(o*Cch + c))*9 + tap] * inv);
        }
        if (tid == 0 && blockIdx.x == 0)
            g_bias2[o] = bias[o]*inv + beta[o] - mean[o]*inv;
        return;
    }
    if (blockIdx.y == 9) {
        int j = blockIdx.z;
        if (j >= 32 || blockIdx.x != 0) return;
        int tid = threadIdx.y * 32 + threadIdx.x;
        for (int kd = tid; kd < Kd; kd += 256) {
            int tap = kd >> 8, c = kd & 255;
            __half v = __float2half_rn(0.f);
            if (j < 18) v = __float2half_rn(w_off[((size_t)(j*Cch + c))*9 + tap]);
            g_Boff[(size_t)j*Kd + kd] = v;
        }
        return;
    }
    __shared__ float t[32][33];
    int x0 = blockIdx.x * 32;
    int c0 = blockIdx.y * 32;
    int bh = blockIdx.z;
    int b = bh >> 6, y = bh & 63;
    #pragma unroll
    for (int i = threadIdx.y; i < 32; i += 8)
        t[i][threadIdx.x] = in[(((size_t)(b*Cch + c0 + i)*Hh + y)*Ww) + x0 + threadIdx.x];
    __syncthreads();
    #pragma unroll
    for (int i = threadIdx.y; i < 32; i += 8) {
        float v = t[threadIdx.x][i];
        __half hi = __float2half_rn(v);
        __half lo = __float2half_rn(v - __half2float(hi));
        size_t o = (((size_t)(b*Hh + y)*Ww + x0 + i) << 8) + c0 + threadIdx.x;
        g_nhwcH[o] = hi;
        g_nhwcL[o] = lo;
    }
}

// ---------------- 2) offset conv as mma GEMM: M=16384, N=32(18), K=2304 ----------------
// A = regular-grid im2col of nhwc hi/lo, zero-filled at borders via cp.async src-size 0.
#define KC2 32
#define NCH2 (Kd/KC2)        // 72
#define APL2 10240           // 128 rows x 80B
#define BSM2 2560            // 32 rows x 80B
#define STG2 (2*APL2 + BSM2) // 23040
#define NSTG2 3

__global__ __launch_bounds__(128, 1) void k_offset_gemm(const float* __restrict__ b_off) {
    extern __shared__ char dsm[];
    const uint32_t sbase = smem_u32(dsm);
    const int tid = threadIdx.x, lid = tid & 31, wid = tid >> 5;
    const int m0 = blockIdx.x * 128;
    const int b = m0 >> 12, y0 = (m0 >> 6) & 63;   // 128 rows = 2 y-rows x 64 x

    float acc[2][4][4];
    #pragma unroll
    for (int mt = 0; mt < 2; mt++)
        #pragma unroll
        for (int nt = 0; nt < 4; nt++)
            #pragma unroll
            for (int j = 0; j < 4; j++) acc[mt][nt][j] = 0.f;

    const uint32_t a_off = (uint32_t)((wid*32 + (lid & 15)) * 80 + (lid >> 4) * 16);
    const uint32_t b_offs = (uint32_t)(((lid & 7) + ((lid >> 4) & 1)*8) * 80
                                       + ((lid >> 3) & 1) * 16);

    auto load = [&](int c, int p) {
        uint32_t sb = sbase + p * STG2;
        int tap = c >> 3;
        int ky = tap / 3 - 1, kx = tap % 3 - 1;
        int c0 = (c & 7) * 32;
        // A: 1024 ops (2 planes x 128 rows x 4 x 16B)
        #pragma unroll
        for (int i = 0; i < 8; i++) {
            int idx = tid + i*128;
            int pl  = idx >> 9;
            int rem = idx & 511;
            int r   = rem >> 2;
            int j   = rem & 3;
            int ry = y0 + (r >> 6) + ky;
            int rx = (r & 63) + kx;
            int valid = ((unsigned)ry < 64u) && ((unsigned)rx < 64u);
            int ryc = min(max(ry, 0), 63), rxc = min(max(rx, 0), 63);
            const __half* base = pl ? g_nhwcL : g_nhwcH;
            const __half* src = base + (((size_t)(b*Hh + ryc)*Ww + rxc) << 8) + c0 + j*8;
            cpa16z(sb + pl*APL2 + r*80 + j*16, src, valid);
        }
        // B: 128 ops (32 rows x 4 x 16B)
        {
            int rr = tid >> 2;
            int j  = tid & 3;
            cpa16(sb + 2*APL2 + rr*80 + j*16, g_Boff + (size_t)rr*Kd + tap*Cch + c0 + j*8);
        }
        asm volatile("cp.async.commit_group;");
    };

    load(0, 0);
    load(1, 1);

    for (int c = 0; c < NCH2; c++) {
        int p = c % NSTG2;
        if (c + 2 < NCH2) {
            load(c + 2, (c + 2) % NSTG2);
            asm volatile("cp.async.wait_group 2;" ::: "memory");
        } else if (c + 1 < NCH2) {
            asm volatile("cp.async.wait_group 1;" ::: "memory");
        } else {
            asm volatile("cp.async.wait_group 0;" ::: "memory");
        }
        __syncthreads();

        uint32_t sb = sbase + p * STG2;
        #pragma unroll
        for (int kh = 0; kh < 2; kh++) {
            uint32_t ah[2][4], al[2][4];
            #pragma unroll
            for (int mt = 0; mt < 2; mt++) {
                uint32_t addr = sb + a_off + mt*(16*80) + kh*32;
                LDMX4(ah[mt], addr);
                LDMX4(al[mt], addr + APL2);
            }
            #pragma unroll
            for (int tp = 0; tp < 2; tp++) {
                uint32_t bb[4];
                LDMX4(bb, sb + 2*APL2 + b_offs + tp*(16*80) + kh*32);
                #pragma unroll
                for (int q = 0; q < 2; q++) {
                    int nt = tp*2 + q;
                    #pragma unroll
                    for (int mt = 0; mt < 2; mt++) {
                        MMA16816(acc[mt][nt], ah[mt], bb[2*q], bb[2*q+1]);
                        MMA16816(acc[mt][nt], al[mt], bb[2*q], bb[2*q+1]);
                    }
                }
            }
        }
        __syncthreads();
    }

    // epilogue: write g_off[b][j][y][x] for j < 18 (+ b_offset)
    #pragma unroll
    for (int mt = 0; mt < 2; mt++) {
        int mA = m0 + wid*32 + mt*16 + (lid >> 2);
        int mB = mA + 8;
        int pA = mA & 4095, pB = mB & 4095;
        #pragma unroll
        for (int nt = 0; nt < 4; nt++) {
            int j0 = nt*8 + (lid & 3)*2;
            float* d = acc[mt][nt];
            if (j0 < 18) {
                float bv = b_off[j0];
                g_off[((size_t)(b*18 + j0) << 12) + pA] = d[0] + bv;
                g_off[((size_t)(b*18 + j0) << 12) + pB] = d[2] + bv;
            }
            if (j0 + 1 < 18) {
                float bv = b_off[j0 + 1];
                g_off[((size_t)(b*18 + j0 + 1) << 12) + pA] = d[1] + bv;
                g_off[((size_t)(b*18 + j0 + 1) << 12) + pB] = d[3] + bv;
            }
        }
    }
}

// ---------------- 3) bilinear sample (fp16 gather) -> fp16 im2col ----------------
__global__ __launch_bounds__(256) void k_sample() {
    int m = blockIdx.x * 4 + (threadIdx.x >> 6);
    int b = m >> 12, y = (m >> 6) & 63, x = m & 63;
    int c = (threadIdx.x & 63) * 4;

    #pragma unroll
    for (int k = 0; k < Kt; k++) {
        float dy = g_off[(((size_t)(b*18 + 2*k    )*Hh + y)*Ww) + x];
        float dx = g_off[(((size_t)(b*18 + 2*k + 1)*Hh + y)*Ww) + x];
        float py = (float)(y - 1 + (k/3)) + dy;
        float px = (float)(x - 1 + (k%3)) + dx;
        float y0f = floorf(py), x0f = floorf(px);
        float ly = py - y0f, lx = px - x0f;
        int y0 = (int)y0f, x0i = (int)x0f;
        int y1 = y0 + 1,  x1 = x0i + 1;
        float vy0 = (y0  >= 0 && y0  < 64) ? 1.f : 0.f;
        float vy1 = (y1  >= 0 && y1  < 64) ? 1.f : 0.f;
        float vx0 = (x0i >= 0 && x0i < 64) ? 1.f : 0.f;
        float vx1 = (x1  >= 0 && x1  < 64) ? 1.f : 0.f;
        float w00 = (1.f-ly)*(1.f-lx)*vy0*vx0;
        float w01 = (1.f-ly)*lx      *vy0*vx1;
        float w10 = ly      *(1.f-lx)*vy1*vx0;
        float w11 = ly      *lx      *vy1*vx1;
        int y0c = min(max(y0, 0), 63), y1c = min(max(y1, 0), 63);
        int x0c = min(max(x0i,0), 63), x1c = min(max(x1, 0), 63);
        const __half* p00 = g_nhwcH + (((size_t)(b*Hh + y0c)*Ww + x0c) << 8) + c;
        const __half* p01 = g_nhwcH + (((size_t)(b*Hh + y0c)*Ww + x1c) << 8) + c;
        const __half* p10 = g_nhwcH + (((size_t)(b*Hh + y1c)*Ww + x0c) << 8) + c;
        const __half* p11 = g_nhwcH + (((size_t)(b*Hh + y1c)*Ww + x1c) << 8) + c;
        uint2 u00 = *(const uint2*)p00;
        uint2 u01 = *(const uint2*)p01;
        uint2 u10 = *(const uint2*)p10;
        uint2 u11 = *(const uint2*)p11;
        float2 f00a = __half22float2(*(__half2*)&u00.x), f00b = __half22float2(*(__half2*)&u00.y);
        float2 f01a = __half22float2(*(__half2*)&u01.x), f01b = __half22float2(*(__half2*)&u01.y);
        float2 f10a = __half22float2(*(__half2*)&u10.x), f10b = __half22float2(*(__half2*)&u10.y);
        float2 f11a = __half22float2(*(__half2*)&u11.x), f11b = __half22float2(*(__half2*)&u11.y);
        float4 r;
        r.x = w00*f00a.x + w01*f01a.x + w10*f10a.x + w11*f11a.x;
        r.y = w00*f00a.y + w01*f01a.y + w10*f10a.y + w11*f11a.y;
        r.z = w00*f00b.x + w01*f01b.x + w10*f10b.x + w11*f11b.x;
        r.w = w00*f00b.y + w01*f01b.y + w10*f10b.y + w11*f11b.y;

        __half2 h01 = __halves2half2(__float2half_rn(r.x), __float2half_rn(r.y));
        __half2 h23 = __halves2half2(__float2half_rn(r.z), __float2half_rn(r.w));
        uint2 pk;
        pk.x = *(uint32_t*)&h01;
        pk.y = *(uint32_t*)&h23;
        *(uint2*)(g_A + (size_t)m*Kd + k*Cch + c) = pk;
    }
}

// ---------------- 4) main fp16 mma GEMM (R6 config: 256 thr, 4-stage) ----------------
#define KC 32
#define NCH (Kd/KC)          // 72
#define APL 10240
#define BPL 20480
#define BOFF APL
#define STG (APL + BPL)      // 30720
#define NSTG 4

__global__ __launch_bounds__(256, 1) void k_gemm_mma(float* __restrict__ out) {
    extern __shared__ char dsm[];
    const uint32_t sbase = smem_u32(dsm);
    const int tid = threadIdx.x, lid = tid & 31, wid = tid >> 5;
    const int warpM = wid & 1, warpN = wid >> 1;   // 2 x 4 -> warp tile 64x64
    const int m0 = blockIdx.x * 128;

    float acc[4][8][4];
    #pragma unroll
    for (int mt = 0; mt < 4; mt++)
        #pragma unroll
        for (int nt = 0; nt < 8; nt++)
            #pragma unroll
            for (int j = 0; j < 4; j++) acc[mt][nt][j] = 0.f;

    const uint32_t a_off = (uint32_t)((warpM*64 + (lid & 15)) * 80 + (lid >> 4) * 16);
    const uint32_t bm_off = (uint32_t)((warpN*64 + (lid & 7) + ((lid >> 4) & 1)*8) * 80
                                       + ((lid >> 3) & 1) * 16);

    auto load = [&](int c, int p) {
        uint32_t sb = sbase + p * STG;
        size_t kOff = (size_t)c * KC;
        #pragma unroll
        for (int i = 0; i < 2; i++) {
            int idx = tid + i*256;
            int rr = idx >> 2;
            int j  = idx & 3;
            cpa16(sb + rr*80 + j*16, g_A + (size_t)(m0 + rr)*Kd + kOff + j*8);
        }
        #pragma unroll
        for (int i = 0; i < 4; i++) {
            int idx = tid + i*256;
            int rr = idx >> 2;
            int j  = idx & 3;
            cpa16(sb + BOFF + rr*80 + j*16, g_B + (size_t)rr*Kd + kOff + j*8);
        }
        asm volatile("cp.async.commit_group;");
    };

    load(0, 0);
    load(1, 1);
    load(2, 2);

    for (int c = 0; c < NCH; c++) {
        int p = c & 3;
        if (c + 3 < NCH) {
            load(c + 3, (c + 3) & 3);
            asm volatile("cp.async.wait_group 3;" ::: "memory");
        } else if (c + 2 < NCH) {
            asm volatile("cp.async.wait_group 2;" ::: "memory");
        } else if (c + 1 < NCH) {
            asm volatile("cp.async.wait_group 1;" ::: "memory");
        } else {
            asm volatile("cp.async.wait_group 0;" ::: "memory");
        }
        __syncthreads();

        uint32_t sb = sbase + p * STG;
        #pragma unroll
        for (int kh = 0; kh < 2; kh++) {
            uint32_t ah[4][4];
            #pragma unroll
            for (int mt = 0; mt < 4; mt++)
                LDMX4(ah[mt], sb + a_off + mt*(16*80) + kh*32);
            #pragma unroll
            for (int tp = 0; tp < 4; tp++) {
                uint32_t bb[4];
                LDMX4(bb, sb + BOFF + bm_off + tp*(16*80) + kh*32);
                #pragma unroll
                for (int q = 0; q < 2; q++) {
                    int nt = tp*2 + q;
                    #pragma unroll
                    for (int mt = 0; mt < 4; mt++)
                        MMA16816(acc[mt][nt], ah[mt], bb[2*q], bb[2*q+1]);
                }
            }
        }
        __syncthreads();
    }

    #pragma unroll
    for (int mt = 0; mt < 4; mt++) {
        int mA = m0 + warpM*64 + mt*16 + (lid >> 2);
        int mB = mA + 8;
        int bA = mA >> 12, bB = mB >> 12;
        int pA = mA & 4095, pB = mB & 4095;
        #pragma unroll
        for (int nt = 0; nt < 8; nt++) {
            int o = warpN*64 + nt*8 + (lid & 3)*2;
            float bv0 = g_bias2[o], bv1 = g_bias2[o + 1];
            float* d = acc[mt][nt];
            out[((size_t)bA << 20) + ((size_t)o << 12)     + pA] = fmaxf(d[0] + bv0, 0.f);
            out[((size_t)bA << 20) + ((size_t)(o+1) << 12) + pA] = fmaxf(d[1] + bv1, 0.f);
            out[((size_t)bB << 20) + ((size_t)o << 12)     + pB] = fmaxf(d[2] + bv0, 0.f);
            out[((size_t)bB << 20) + ((size_t)(o+1) << 12) + pB] = fmaxf(d[3] + bv1, 0.f);
        }
    }
}

// ---------------- launch ----------------
extern "C" void kernel_launch(void* const* d_in, const int* in_sizes, int n_in,
                              void* d_out, int out_size) {
    const float* input  = (const float*)d_in[0];
    const float* w_off  = (const float*)d_in[1];
    const float* b_off  = (const float*)d_in[2];
    const float* weight = (const float*)d_in[3];
    const float* bias   = (const float*)d_in[4];
    const float* gamma  = (const float*)d_in[5];
    const float* beta   = (const float*)d_in[6];
    const float* mean   = (const float*)d_in[7];
    const float* var    = (const float*)d_in[8];
    float* out = (float*)d_out;

    cudaFuncSetAttribute(k_gemm_mma, cudaFuncAttributeMaxDynamicSharedMemorySize, NSTG*STG);
    cudaFuncSetAttribute(k_offset_gemm, cudaFuncAttributeMaxDynamicSharedMemorySize, NSTG2*STG2);

    k_transpose_prep<<<dim3(2, 10, 256), dim3(32, 8)>>>(input, weight, w_off, bias, gamma, beta, mean, var);
    k_offset_gemm<<<Md/128, 128, NSTG2*STG2>>>(b_off);
    k_sample<<<Md/4, 256>>>();
    k_gemm_mma<<<Md/128, 256, NSTG*STG>>>(out);
}

// round 9
// speedup vs baseline: 1.9334x; 1.1161x over previous
#include <cuda_runtime.h>
#include <cuda_fp16.h>
#include <cstdint>

#define Bsz 4
#define Cch 256
#define Hh  64
#define Ww  64
#define Oo  256
#define Kt  9
#define Md  (Bsz*Hh*Ww)   // 16384
#define Kd  (Cch*Kt)      // 2304

// ---------------- scratch ----------------
__device__ __half g_nhwcH[(size_t)Bsz*Hh*Ww*Cch];   // fp16 hi plane
__device__ __half g_nhwcL[(size_t)Bsz*Hh*Ww*Cch];   // fp16 residual plane (offset conv only)
__device__ float g_off[(size_t)Bsz*18*Hh*Ww];
__device__ __half g_B[(size_t)Oo*Kd];
__device__ __half g_Boff[(size_t)32*Kd];
__device__ float g_bias2[Oo];

// ---------------- helpers ----------------
__device__ __forceinline__ uint32_t smem_u32(const void* p) {
    uint32_t a;
    asm("{ .reg .u64 t; cvta.to.shared.u64 t, %1; cvt.u32.u64 %0, t; }" : "=r"(a) : "l"(p));
    return a;
}
__device__ __forceinline__ void cpa16(uint32_t s, const void* g) {
    asm volatile("cp.async.cg.shared.global [%0], [%1], 16;" :: "r"(s), "l"(g));
}
__device__ __forceinline__ void cpa16z(uint32_t s, const void* g, int valid) {
    asm volatile("cp.async.cg.shared.global [%0], [%1], 16, %2;"
                 :: "r"(s), "l"(g), "r"(valid ? 16 : 0));
}
#define LDMX4(r, addr) \
    asm volatile("ldmatrix.sync.aligned.m8n8.x4.shared.b16 {%0,%1,%2,%3}, [%4];" \
        : "=r"((r)[0]), "=r"((r)[1]), "=r"((r)[2]), "=r"((r)[3]) : "r"(addr))
#define MMA16816(d, a, b0, b1) \
    asm volatile("mma.sync.aligned.m16n8k16.row.col.f32.f16.f16.f32 " \
        "{%0,%1,%2,%3}, {%4,%5,%6,%7}, {%8,%9}, {%0,%1,%2,%3};" \
        : "+f"((d)[0]), "+f"((d)[1]), "+f"((d)[2]), "+f"((d)[3]) \
        : "r"((a)[0]), "r"((a)[1]), "r"((a)[2]), "r"((a)[3]), "r"(b0), "r"(b1))

// ---------------- 1) transpose to fp16 hi/lo NHWC + weight prep ----------------
__global__ void k_transpose_prep(const float* __restrict__ in,
                                 const float* __restrict__ w,
                                 const float* __restrict__ w_off,
                                 const float* __restrict__ bias,
                                 const float* __restrict__ gamma,
                                 const float* __restrict__ beta,
                                 const float* __restrict__ mean,
                                 const float* __restrict__ var) {
    if (blockIdx.y == 8) {
        int o = blockIdx.z;
        int tid = threadIdx.y * 32 + threadIdx.x;
        float inv = gamma[o] * rsqrtf(var[o] + 1e-5f);
        int kd0 = blockIdx.x * (Kd/2);
        for (int i = tid; i < Kd/2; i += 256) {
            int kd = kd0 + i;
            int tap = kd >> 8, c = kd & 255;
            g_B[(size_t)o*Kd + kd] = __float2half_rn(w[((size_t)(o*Cch + c))*9 + tap] * inv);
        }
        if (tid == 0 && blockIdx.x == 0)
            g_bias2[o] = bias[o]*inv + beta[o] - mean[o]*inv;
        return;
    }
    if (blockIdx.y == 9) {
        int j = blockIdx.z;
        if (j >= 32 || blockIdx.x != 0) return;
        int tid = threadIdx.y * 32 + threadIdx.x;
        for (int kd = tid; kd < Kd; kd += 256) {
            int tap = kd >> 8, c = kd & 255;
            __half v = __float2half_rn(0.f);
            if (j < 18) v = __float2half_rn(w_off[((size_t)(j*Cch + c))*9 + tap]);
            g_Boff[(size_t)j*Kd + kd] = v;
        }
        return;
    }
    __shared__ float t[32][33];
    int x0 = blockIdx.x * 32;
    int c0 = blockIdx.y * 32;
    int bh = blockIdx.z;
    int b = bh >> 6, y = bh & 63;
    #pragma unroll
    for (int i = threadIdx.y; i < 32; i += 8)
        t[i][threadIdx.x] = in[(((size_t)(b*Cch + c0 + i)*Hh + y)*Ww) + x0 + threadIdx.x];
    __syncthreads();
    #pragma unroll
    for (int i = threadIdx.y; i < 32; i += 8) {
        float v = t[threadIdx.x][i];
        __half hi = __float2half_rn(v);
        __half lo = __float2half_rn(v - __half2float(hi));
        size_t o = (((size_t)(b*Hh + y)*Ww + x0 + i) << 8) + c0 + threadIdx.x;
        g_nhwcH[o] = hi;
        g_nhwcL[o] = lo;
    }
}

// ---------------- 2) offset conv as mma GEMM ----------------
#define KC2 32
#define NCH2 (Kd/KC2)
#define APL2 10240
#define BSM2 2560
#define STG2 (2*APL2 + BSM2)
#define NSTG2 3

__global__ __launch_bounds__(128, 1) void k_offset_gemm(const float* __restrict__ b_off) {
    extern __shared__ char dsm[];
    const uint32_t sbase = smem_u32(dsm);
    const int tid = threadIdx.x, lid = tid & 31, wid = tid >> 5;
    const int m0 = blockIdx.x * 128;
    const int b = m0 >> 12, y0 = (m0 >> 6) & 63;

    float acc[2][4][4];
    #pragma unroll
    for (int mt = 0; mt < 2; mt++)
        #pragma unroll
        for (int nt = 0; nt < 4; nt++)
            #pragma unroll
            for (int j = 0; j < 4; j++) acc[mt][nt][j] = 0.f;

    const uint32_t a_off = (uint32_t)((wid*32 + (lid & 15)) * 80 + (lid >> 4) * 16);
    const uint32_t b_offs = (uint32_t)(((lid & 7) + ((lid >> 4) & 1)*8) * 80
                                       + ((lid >> 3) & 1) * 16);

    auto load = [&](int c, int p) {
        uint32_t sb = sbase + p * STG2;
        int tap = c >> 3;
        int ky = tap / 3 - 1, kx = tap % 3 - 1;
        int c0 = (c & 7) * 32;
        #pragma unroll
        for (int i = 0; i < 8; i++) {
            int idx = tid + i*128;
            int pl  = idx >> 9;
            int rem = idx & 511;
            int r   = rem >> 2;
            int j   = rem & 3;
            int ry = y0 + (r >> 6) + ky;
            int rx = (r & 63) + kx;
            int valid = ((unsigned)ry < 64u) && ((unsigned)rx < 64u);
            int ryc = min(max(ry, 0), 63), rxc = min(max(rx, 0), 63);
            const __half* base = pl ? g_nhwcL : g_nhwcH;
            const __half* src = base + (((size_t)(b*Hh + ryc)*Ww + rxc) << 8) + c0 + j*8;
            cpa16z(sb + pl*APL2 + r*80 + j*16, src, valid);
        }
        {
            int rr = tid >> 2;
            int j  = tid & 3;
            cpa16(sb + 2*APL2 + rr*80 + j*16, g_Boff + (size_t)rr*Kd + tap*Cch + c0 + j*8);
        }
        asm volatile("cp.async.commit_group;");
    };

    load(0, 0);
    load(1, 1);

    for (int c = 0; c < NCH2; c++) {
        int p = c % NSTG2;
        if (c + 2 < NCH2) {
            load(c + 2, (c + 2) % NSTG2);
            asm volatile("cp.async.wait_group 2;" ::: "memory");
        } else if (c + 1 < NCH2) {
            asm volatile("cp.async.wait_group 1;" ::: "memory");
        } else {
            asm volatile("cp.async.wait_group 0;" ::: "memory");
        }
        __syncthreads();

        uint32_t sb = sbase + p * STG2;
        #pragma unroll
        for (int kh = 0; kh < 2; kh++) {
            uint32_t ah[2][4], al[2][4];
            #pragma unroll
            for (int mt = 0; mt < 2; mt++) {
                uint32_t addr = sb + a_off + mt*(16*80) + kh*32;
                LDMX4(ah[mt], addr);
                LDMX4(al[mt], addr + APL2);
            }
            #pragma unroll
            for (int tp = 0; tp < 2; tp++) {
                uint32_t bb[4];
                LDMX4(bb, sb + 2*APL2 + b_offs + tp*(16*80) + kh*32);
                #pragma unroll
                for (int q = 0; q < 2; q++) {
                    int nt = tp*2 + q;
                    #pragma unroll
                    for (int mt = 0; mt < 2; mt++) {
                        MMA16816(acc[mt][nt], ah[mt], bb[2*q], bb[2*q+1]);
                        MMA16816(acc[mt][nt], al[mt], bb[2*q], bb[2*q+1]);
                    }
                }
            }
        }
        __syncthreads();
    }

    #pragma unroll
    for (int mt = 0; mt < 2; mt++) {
        int mA = m0 + wid*32 + mt*16 + (lid >> 2);
        int mB = mA + 8;
        int pA = mA & 4095, pB = mB & 4095;
        #pragma unroll
        for (int nt = 0; nt < 4; nt++) {
            int j0 = nt*8 + (lid & 3)*2;
            float* d = acc[mt][nt];
            if (j0 < 18) {
                float bv = b_off[j0];
                g_off[((size_t)(b*18 + j0) << 12) + pA] = d[0] + bv;
                g_off[((size_t)(b*18 + j0) << 12) + pB] = d[2] + bv;
            }
            if (j0 + 1 < 18) {
                float bv = b_off[j0 + 1];
                g_off[((size_t)(b*18 + j0 + 1) << 12) + pA] = d[1] + bv;
                g_off[((size_t)(b*18 + j0 + 1) << 12) + pB] = d[3] + bv;
            }
        }
    }
}

// ---------------- 3) fused sample + fp16 mma GEMM ----------------
// A tiles (128 x 32 per chunk) computed in-kernel from g_nhwcH via bilinear gather.
// Lane map for gather: warp covers rows wid*16 + it*8 + (lane>>3)... (see below)
//   per it (0/1): row = wid*16 + it*8 + (lane>>2); lane&3 -> 8-channel slice (16B).
#define KC 32
#define NCH (Kd/KC)          // 72
#define APL 10240            // A buffer (128 rows x 80B), double buffered
#define BPL 20480            // B stage (256 rows x 80B)
#define BBASE (2*APL)
#define NSTGB 4
#define SMEMSZ (2*APL + NSTGB*BPL)   // 102400

__global__ __launch_bounds__(256, 1) void k_gemm_fused(float* __restrict__ out) {
    extern __shared__ char dsm[];
    const uint32_t sbase = smem_u32(dsm);
    char* dsmp = dsm;
    const int tid = threadIdx.x, lid = tid & 31, wid = tid >> 5;
    const int warpM = wid & 1, warpN = wid >> 1;   // 2 x 4, warp tile 64x64
    const int m0 = blockIdx.x * 128;
    const int bb = m0 >> 12;             // batch index (constant per CTA)
    const int pbase = m0 & 4095;         // within-batch pixel base

    float acc[4][8][4];
    #pragma unroll
    for (int mt = 0; mt < 4; mt++)
        #pragma unroll
        for (int nt = 0; nt < 8; nt++)
            #pragma unroll
            for (int j = 0; j < 4; j++) acc[mt][nt][j] = 0.f;

    const uint32_t a_off = (uint32_t)((warpM*64 + (lid & 15)) * 80 + (lid >> 4) * 16);
    const uint32_t bm_off = (uint32_t)((warpN*64 + (lid & 7) + ((lid >> 4) & 1)*8) * 80
                                       + ((lid >> 3) & 1) * 16);

    // gather state: per it (2 rows per lane), 4 corner weights + byte bases
    float gw[2][4];
    uint32_t gb[2][4];
    const int growl[2] = { wid*16 + (lid >> 2), wid*16 + 8 + (lid >> 2) };
    const uint32_t chb = (uint32_t)((lid & 3) * 16);   // 16B slice within 64B chunk row

    auto calc_tap = [&](int tap) {
        #pragma unroll
        for (int it = 0; it < 2; it++) {
            int p = pbase + growl[it];
            int y = (p >> 6) & 63, x = p & 63;
            float dy = g_off[((size_t)(bb*18 + 2*tap) << 12) + p];
            float dx = g_off[((size_t)(bb*18 + 2*tap + 1) << 12) + p];
            float py = (float)(y - 1 + tap/3) + dy;
            float px = (float)(x - 1 + tap%3) + dx;
            float y0f = floorf(py), x0f = floorf(px);
            float ly = py - y0f, lx = px - x0f;
            int y0 = (int)y0f, x0i = (int)x0f;
            int y1 = y0 + 1,  x1 = x0i + 1;
            float vy0 = (y0  >= 0 && y0  < 64) ? 1.f : 0.f;
            float vy1 = (y1  >= 0 && y1  < 64) ? 1.f : 0.f;
            float vx0 = (x0i >= 0 && x0i < 64) ? 1.f : 0.f;
            float vx1 = (x1  >= 0 && x1  < 64) ? 1.f : 0.f;
            gw[it][0] = (1.f-ly)*(1.f-lx)*vy0*vx0;
            gw[it][1] = (1.f-ly)*lx      *vy0*vx1;
            gw[it][2] = ly      *(1.f-lx)*vy1*vx0;
            gw[it][3] = ly      *lx      *vy1*vx1;
            int y0c = min(max(y0, 0), 63), y1c = min(max(y1, 0), 63);
            int x0c = min(max(x0i,0), 63), x1c = min(max(x1, 0), 63);
            uint32_t rowb = (uint32_t)(bb << 12);
            gb[it][0] = (rowb + (y0c << 6) + x0c) << 9;   // *512 bytes per pixel
            gb[it][1] = (rowb + (y0c << 6) + x1c) << 9;
            gb[it][2] = (rowb + (y1c << 6) + x0c) << 9;
            gb[it][3] = (rowb + (y1c << 6) + x1c) << 9;
        }
    };

    const char* nb = (const char*)g_nhwcH;

    // gather 4 corners (16B each) for iteration it of chunk with channel base c0
    auto gather = [&](int it, int c0, uint4* cd) {
        uint32_t cho = (uint32_t)(c0 * 2) + chb;
        cd[0] = *(const uint4*)(nb + gb[it][0] + cho);
        cd[1] = *(const uint4*)(nb + gb[it][1] + cho);
        cd[2] = *(const uint4*)(nb + gb[it][2] + cho);
        cd[3] = *(const uint4*)(nb + gb[it][3] + cho);
    };

    // combine corners -> 8 fp16 vals, store to A buffer
    auto combine_sts = [&](int it, const uint4* cd, uint32_t abuf_off) {
        uint4 pk;
        uint32_t* po = (uint32_t*)&pk;
        #pragma unroll
        for (int j = 0; j < 4; j++) {
            float2 f0 = __half22float2(((const __half2*)&cd[0])[j]);
            float2 f1 = __half22float2(((const __half2*)&cd[1])[j]);
            float2 f2 = __half22float2(((const __half2*)&cd[2])[j]);
            float2 f3 = __half22float2(((const __half2*)&cd[3])[j]);
            float rx = gw[it][0]*f0.x + gw[it][1]*f1.x + gw[it][2]*f2.x + gw[it][3]*f3.x;
            float ry = gw[it][0]*f0.y + gw[it][1]*f1.y + gw[it][2]*f2.y + gw[it][3]*f3.y;
            __half2 h = __floats2half2_rn(rx, ry);
            po[j] = *(uint32_t*)&h;
        }
        *(uint4*)(dsmp + abuf_off + growl[it]*80 + (lid & 3)*16) = pk;
    };

    auto loadB = [&](int c, int p) {
        uint32_t sb = sbase + BBASE + p * BPL;
        size_t kOff = (size_t)c * KC;
        #pragma unroll
        for (int i = 0; i < 4; i++) {
            int idx = tid + i*256;
            int rr = idx >> 2;
            int j  = idx & 3;
            cpa16(sb + rr*80 + j*16, g_B + (size_t)rr*Kd + kOff + j*8);
        }
        asm volatile("cp.async.commit_group;");
    };

    // prologue: A(0) + B(0..2)
    calc_tap(0);
    {
        uint4 cd[4];
        gather(0, 0, cd); combine_sts(0, cd, 0);
        gather(1, 0, cd); combine_sts(1, cd, 0);
    }
    loadB(0, 0);
    loadB(1, 1);
    loadB(2, 2);

    for (int c = 0; c < NCH; c++) {
        if (c + 3 < NCH) {
            asm volatile("cp.async.wait_group 2;" ::: "memory");
        } else if (c + 2 < NCH) {
            asm volatile("cp.async.wait_group 1;" ::: "memory");
        } else {
            asm volatile("cp.async.wait_group 0;" ::: "memory");
        }
        __syncthreads();

        const int prep = (c + 1 < NCH);
        const int cn = c + 1;
        if (prep && ((cn & 7) == 0)) calc_tap(cn >> 3);
        const int c0n = (cn & 7) * 32;
        const uint32_t abuf_n = (uint32_t)((cn & 1) * APL);

        uint32_t sbB = sbase + BBASE + (c & 3) * BPL;
        uint32_t sbA = sbase + (c & 1) * APL;

        uint4 cd0[4], cd1[4];
        if (prep) gather(0, c0n, cd0);          // LDGs issued early, hidden by MMA

        // kh = 0
        {
            uint32_t ah[4][4];
            #pragma unroll
            for (int mt = 0; mt < 4; mt++)
                LDMX4(ah[mt], sbA + a_off + mt*(16*80));
            #pragma unroll
            for (int tp = 0; tp < 4; tp++) {
                uint32_t bfr[4];
                LDMX4(bfr, sbB + bm_off + tp*(16*80));
                #pragma unroll
                for (int q = 0; q < 2; q++) {
                    int nt = tp*2 + q;
                    #pragma unroll
                    for (int mt = 0; mt < 4; mt++)
                        MMA16816(acc[mt][nt], ah[mt], bfr[2*q], bfr[2*q+1]);
                }
            }
        }
        if (prep) { combine_sts(0, cd0, abuf_n); gather(1, c0n, cd1); }
        // kh = 1
        {
            uint32_t ah[4][4];
            #pragma unroll
            for (int mt = 0; mt < 4; mt++)
                LDMX4(ah[mt], sbA + a_off + mt*(16*80) + 32);
            #pragma unroll
            for (int tp = 0; tp < 4; tp++) {
                uint32_t bfr[4];
                LDMX4(bfr, sbB + bm_off + tp*(16*80) + 32);
                #pragma unroll
                for (int q = 0; q < 2; q++) {
                    int nt = tp*2 + q;
                    #pragma unroll
                    for (int mt = 0; mt < 4; mt++)
                        MMA16816(acc[mt][nt], ah[mt], bfr[2*q], bfr[2*q+1]);
                }
            }
        }
        if (prep) combine_sts(1, cd1, abuf_n);
        if (c + 3 < NCH) loadB(c + 3, (c + 3) & 3);
    }

    // epilogue: bias + relu, NCHW stores
    #pragma unroll
    for (int mt = 0; mt < 4; mt++) {
        int mA = m0 + warpM*64 + mt*16 + (lid >> 2);
        int mB = mA + 8;
        int bA = mA >> 12, bB = mB >> 12;
        int pA = mA & 4095, pB = mB & 4095;
        #pragma unroll
        for (int nt = 0; nt < 8; nt++) {
            int o = warpN*64 + nt*8 + (lid & 3)*2;
            float bv0 = g_bias2[o], bv1 = g_bias2[o + 1];
            float* d = acc[mt][nt];
            out[((size_t)bA << 20) + ((size_t)o << 12)     + pA] = fmaxf(d[0] + bv0, 0.f);
            out[((size_t)bA << 20) + ((size_t)(o+1) << 12) + pA] = fmaxf(d[1] + bv1, 0.f);
            out[((size_t)bB << 20) + ((size_t)o << 12)     + pB] = fmaxf(d[2] + bv0, 0.f);
            out[((size_t)bB << 20) + ((size_t)(o+1) << 12) + pB] = fmaxf(d[3] + bv1, 0.f);
        }
    }
}

// ---------------- launch ----------------
extern "C" void kernel_launch(void* const* d_in, const int* in_sizes, int n_in,
                              void* d_out, int out_size) {
    const float* input  = (const float*)d_in[0];
    const float* w_off  = (const float*)d_in[1];
    const float* b_off  = (const float*)d_in[2];
    const float* weight = (const float*)d_in[3];
    const float* bias   = (const float*)d_in[4];
    const float* gamma  = (const float*)d_in[5];
    const float* beta   = (const float*)d_in[6];
    const float* mean   = (const float*)d_in[7];
    const float* var    = (const float*)d_in[8];
    float* out = (float*)d_out;

    cudaFuncSetAttribute(k_gemm_fused, cudaFuncAttributeMaxDynamicSharedMemorySize, SMEMSZ);
    cudaFuncSetAttribute(k_offset_gemm, cudaFuncAttributeMaxDynamicSharedMemorySize, NSTG2*STG2);

    k_transpose_prep<<<dim3(2, 10, 256), dim3(32, 8)>>>(input, weight, w_off, bias, gamma, beta, mean, var);
    k_offset_gemm<<<Md/128, 128, NSTG2*STG2>>>(b_off);
    k_gemm_fused<<<Md/128, 256, SMEMSZ>>>(out);
}

// round 12
// speedup vs baseline: 2.1825x; 1.1289x over previous
#include <cuda_runtime.h>
#include <cuda_fp16.h>
#include <cstdint>

#define Bsz 4
#define Cch 256
#define Hh  64
#define Ww  64
#define Oo  256
#define Kt  9
#define Md  (Bsz*Hh*Ww)   // 16384
#define Kd  (Cch*Kt)      // 2304

// ---------------- scratch ----------------
__device__ __half g_nhwcH[(size_t)Bsz*Hh*Ww*Cch];   // fp16 NHWC
__device__ float g_off[(size_t)Bsz*18*Hh*Ww];
__device__ __half g_B[(size_t)Oo*Kd];
__device__ __half g_Boff[(size_t)32*Kd];
__device__ float g_bias2[Oo];

// ---------------- helpers ----------------
__device__ __forceinline__ uint32_t smem_u32(const void* p) {
    uint32_t a;
    asm("{ .reg .u64 t; cvta.to.shared.u64 t, %1; cvt.u32.u64 %0, t; }" : "=r"(a) : "l"(p));
    return a;
}
__device__ __forceinline__ void cpa16(uint32_t s, const void* g) {
    asm volatile("cp.async.cg.shared.global [%0], [%1], 16;" :: "r"(s), "l"(g));
}
__device__ __forceinline__ void cpa16z(uint32_t s, const void* g, int valid) {
    asm volatile("cp.async.cg.shared.global [%0], [%1], 16, %2;"
                 :: "r"(s), "l"(g), "r"(valid ? 16 : 0));
}
#define LDMX4(r, addr) \
    asm volatile("ldmatrix.sync.aligned.m8n8.x4.shared.b16 {%0,%1,%2,%3}, [%4];" \
        : "=r"((r)[0]), "=r"((r)[1]), "=r"((r)[2]), "=r"((r)[3]) : "r"(addr))
#define MMA16816(d, a, b0, b1) \
    asm volatile("mma.sync.aligned.m16n8k16.row.col.f32.f16.f16.f32 " \
        "{%0,%1,%2,%3}, {%4,%5,%6,%7}, {%8,%9}, {%0,%1,%2,%3};" \
        : "+f"((d)[0]), "+f"((d)[1]), "+f"((d)[2]), "+f"((d)[3]) \
        : "r"((a)[0]), "r"((a)[1]), "r"((a)[2]), "r"((a)[3]), "r"(b0), "r"(b1))

// ---------------- 1) transpose to fp16 NHWC + weight prep ----------------
__global__ void k_transpose_prep(const float* __restrict__ in,
                                 const float* __restrict__ w,
                                 const float* __restrict__ w_off,
                                 const float* __restrict__ bias,
                                 const float* __restrict__ gamma,
                                 const float* __restrict__ beta,
                                 const float* __restrict__ mean,
                                 const float* __restrict__ var) {
    if (blockIdx.y == 8) {
        int o = blockIdx.z;
        int tid = threadIdx.y * 32 + threadIdx.x;
        float inv = gamma[o] * rsqrtf(var[o] + 1e-5f);
        int kd0 = blockIdx.x * (Kd/2);
        for (int i = tid; i < Kd/2; i += 256) {
            int kd = kd0 + i;
            int tap = kd >> 8, c = kd & 255;
            g_B[(size_t)o*Kd + kd] = __float2half_rn(w[((size_t)(o*Cch + c))*9 + tap] * inv);
        }
        if (tid == 0 && blockIdx.x == 0)
            g_bias2[o] = bias[o]*inv + beta[o] - mean[o]*inv;
        return;
    }
    if (blockIdx.y == 9) {
        int j = blockIdx.z;
        if (j >= 32 || blockIdx.x != 0) return;
        int tid = threadIdx.y * 32 + threadIdx.x;
        for (int kd = tid; kd < Kd; kd += 256) {
            int tap = kd >> 8, c = kd & 255;
            __half v = __float2half_rn(0.f);
            if (j < 18) v = __float2half_rn(w_off[((size_t)(j*Cch + c))*9 + tap]);
            g_Boff[(size_t)j*Kd + kd] = v;
        }
        return;
    }
    __shared__ float t[32][33];
    int x0 = blockIdx.x * 32;
    int c0 = blockIdx.y * 32;
    int bh = blockIdx.z;
    int b = bh >> 6, y = bh & 63;
    #pragma unroll
    for (int i = threadIdx.y; i < 32; i += 8)
        t[i][threadIdx.x] = in[(((size_t)(b*Cch + c0 + i)*Hh + y)*Ww) + x0 + threadIdx.x];
    __syncthreads();
    #pragma unroll
    for (int i = threadIdx.y; i < 32; i += 8) {
        size_t o = (((size_t)(b*Hh + y)*Ww + x0 + i) << 8) + c0 + threadIdx.x;
        g_nhwcH[o] = __float2half_rn(t[threadIdx.x][i]);
    }
}

// ---------------- 2) offset conv as 1-term fp16 mma GEMM (256 thr) ----------------
#define KC2 32
#define NCH2 (Kd/KC2)        // 72
#define APL2 10240           // 128 rows x 80B
#define BSM2 2560            // 32 rows x 80B
#define STG2 (APL2 + BSM2)   // 12800
#define NSTG2 4

__global__ __launch_bounds__(256, 1) void k_offset_gemm(const float* __restrict__ b_off) {
    extern __shared__ char dsm[];
    const uint32_t sbase = smem_u32(dsm);
    const int tid = threadIdx.x, lid = tid & 31, wid = tid >> 5;   // 8 warps
    const int m0 = blockIdx.x * 128;
    const int b = m0 >> 12, y0 = (m0 >> 6) & 63;

    float acc[4][4];    // warp tile 16x32: nt = 4
    #pragma unroll
    for (int nt = 0; nt < 4; nt++)
        #pragma unroll
        for (int j = 0; j < 4; j++) acc[nt][j] = 0.f;

    const uint32_t a_off = (uint32_t)((wid*16 + (lid & 15)) * 80 + (lid >> 4) * 16);
    const uint32_t b_offs = (uint32_t)(((lid & 7) + ((lid >> 4) & 1)*8) * 80
                                       + ((lid >> 3) & 1) * 16);

    auto load = [&](int c, int p) {
        uint32_t sb = sbase + p * STG2;
        int tap = c >> 3;
        int ky = tap / 3 - 1, kx = tap % 3 - 1;
        int c0 = (c & 7) * 32;
        // A: 512 ops (128 rows x 4 x 16B), 2 per thread
        #pragma unroll
        for (int i = 0; i < 2; i++) {
            int idx = tid + i*256;
            int r   = idx >> 2;
            int j   = idx & 3;
            int ry = y0 + (r >> 6) + ky;
            int rx = (r & 63) + kx;
            int valid = ((unsigned)ry < 64u) && ((unsigned)rx < 64u);
            int ryc = min(max(ry, 0), 63), rxc = min(max(rx, 0), 63);
            const __half* src = g_nhwcH + (((size_t)(b*Hh + ryc)*Ww + rxc) << 8) + c0 + j*8;
            cpa16z(sb + r*80 + j*16, src, valid);
        }
        // B: 128 ops (32 rows x 4 x 16B)
        if (tid < 128) {
            int rr = tid >> 2;
            int j  = tid & 3;
            cpa16(sb + APL2 + rr*80 + j*16, g_Boff + (size_t)rr*Kd + tap*Cch + c0 + j*8);
        }
        asm volatile("cp.async.commit_group;");
    };

    load(0, 0);
    load(1, 1);
    load(2, 2);

    for (int c = 0; c < NCH2; c++) {
        int p = c & 3;
        if (c + 3 < NCH2) {
            load(c + 3, (c + 3) & 3);
            asm volatile("cp.async.wait_group 3;" ::: "memory");
        } else if (c + 2 < NCH2) {
            asm volatile("cp.async.wait_group 2;" ::: "memory");
        } else if (c + 1 < NCH2) {
            asm volatile("cp.async.wait_group 1;" ::: "memory");
        } else {
            asm volatile("cp.async.wait_group 0;" ::: "memory");
        }
        __syncthreads();

        uint32_t sb = sbase + p * STG2;
        #pragma unroll
        for (int kh = 0; kh < 2; kh++) {
            uint32_t ah[4];
            LDMX4(ah, sb + a_off + kh*32);
            #pragma unroll
            for (int tp = 0; tp < 2; tp++) {
                uint32_t bb[4];
                LDMX4(bb, sb + APL2 + b_offs + tp*(16*80) + kh*32);
                #pragma unroll
                for (int q = 0; q < 2; q++)
                    MMA16816(acc[tp*2 + q], ah, bb[2*q], bb[2*q+1]);
            }
        }
        __syncthreads();
    }

    // epilogue: write g_off[b][j][pix] for j < 18 (+ b_offset)
    {
        int mA = m0 + wid*16 + (lid >> 2);
        int mB = mA + 8;
        int pA = mA & 4095, pB = mB & 4095;
        #pragma unroll
        for (int nt = 0; nt < 4; nt++) {
            int j0 = nt*8 + (lid & 3)*2;
            float* d = acc[nt];
            if (j0 < 18) {
                float bv = b_off[j0];
                g_off[((size_t)(b*18 + j0) << 12) + pA] = d[0] + bv;
                g_off[((size_t)(b*18 + j0) << 12) + pB] = d[2] + bv;
            }
            if (j0 + 1 < 18) {
                float bv = b_off[j0 + 1];
                g_off[((size_t)(b*18 + j0 + 1) << 12) + pA] = d[1] + bv;
                g_off[((size_t)(b*18 + j0 + 1) << 12) + pB] = d[3] + bv;
            }
        }
    }
}

// ---------------- 3) fused sample + fp16 mma GEMM ----------------
#define KC 32
#define NCH (Kd/KC)          // 72
#define APL 10240            // A buffer (128 rows x 80B), double buffered
#define BPL 20480            // B stage (256 rows x 80B)
#define BBASE (2*APL)
#define NSTGB 4
#define SMEMSZ (2*APL + NSTGB*BPL)   // 102400

__global__ __launch_bounds__(256, 1) void k_gemm_fused(float* __restrict__ out) {
    extern __shared__ char dsm[];
    const uint32_t sbase = smem_u32(dsm);
    char* dsmp = dsm;
    const int tid = threadIdx.x, lid = tid & 31, wid = tid >> 5;
    const int warpM = wid & 1, warpN = wid >> 1;   // 2 x 4, warp tile 64x64
    const int m0 = blockIdx.x * 128;
    const int bb = m0 >> 12;
    const int pbase = m0 & 4095;

    float acc[4][8][4];
    #pragma unroll
    for (int mt = 0; mt < 4; mt++)
        #pragma unroll
        for (int nt = 0; nt < 8; nt++)
            #pragma unroll
            for (int j = 0; j < 4; j++) acc[mt][nt][j] = 0.f;

    const uint32_t a_off = (uint32_t)((warpM*64 + (lid & 15)) * 80 + (lid >> 4) * 16);
    const uint32_t bm_off = (uint32_t)((warpN*64 + (lid & 7) + ((lid >> 4) & 1)*8) * 80
                                       + ((lid >> 3) & 1) * 16);

    float gw[2][4];
    uint32_t gb[2][4];
    const int growl[2] = { wid*16 + (lid >> 2), wid*16 + 8 + (lid >> 2) };
    const uint32_t chb = (uint32_t)((lid & 3) * 16);

    auto calc_tap = [&](int tap) {
        #pragma unroll
        for (int it = 0; it < 2; it++) {
            int p = pbase + growl[it];
            int y = (p >> 6) & 63, x = p & 63;
            float dy = g_off[((size_t)(bb*18 + 2*tap) << 12) + p];
            float dx = g_off[((size_t)(bb*18 + 2*tap + 1) << 12) + p];
            float py = (float)(y - 1 + tap/3) + dy;
            float px = (float)(x - 1 + tap%3) + dx;
            float y0f = floorf(py), x0f = floorf(px);
            float ly = py - y0f, lx = px - x0f;
            int y0 = (int)y0f, x0i = (int)x0f;
            int y1 = y0 + 1,  x1 = x0i + 1;
            float vy0 = (y0  >= 0 && y0  < 64) ? 1.f : 0.f;
            float vy1 = (y1  >= 0 && y1  < 64) ? 1.f : 0.f;
            float vx0 = (x0i >= 0 && x0i < 64) ? 1.f : 0.f;
            float vx1 = (x1  >= 0 && x1  < 64) ? 1.f : 0.f;
            gw[it][0] = (1.f-ly)*(1.f-lx)*vy0*vx0;
            gw[it][1] = (1.f-ly)*lx      *vy0*vx1;
            gw[it][2] = ly      *(1.f-lx)*vy1*vx0;
            gw[it][3] = ly      *lx      *vy1*vx1;
            int y0c = min(max(y0, 0), 63), y1c = min(max(y1, 0), 63);
            int x0c = min(max(x0i,0), 63), x1c = min(max(x1, 0), 63);
            uint32_t rowb = (uint32_t)(bb << 12);
            gb[it][0] = (rowb + (y0c << 6) + x0c) << 9;
            gb[it][1] = (rowb + (y0c << 6) + x1c) << 9;
            gb[it][2] = (rowb + (y1c << 6) + x0c) << 9;
            gb[it][3] = (rowb + (y1c << 6) + x1c) << 9;
        }
    };

    const char* nb = (const char*)g_nhwcH;

    auto gather = [&](int it, int c0, uint4* cd) {
        uint32_t cho = (uint32_t)(c0 * 2) + chb;
        cd[0] = *(const uint4*)(nb + gb[it][0] + cho);
        cd[1] = *(const uint4*)(nb + gb[it][1] + cho);
        cd[2] = *(const uint4*)(nb + gb[it][2] + cho);
        cd[3] = *(const uint4*)(nb + gb[it][3] + cho);
    };

    auto combine_sts = [&](int it, const uint4* cd, uint32_t abuf_off) {
        uint4 pk;
        uint32_t* po = (uint32_t*)&pk;
        #pragma unroll
        for (int j = 0; j < 4; j++) {
            float2 f0 = __half22float2(((const __half2*)&cd[0])[j]);
            float2 f1 = __half22float2(((const __half2*)&cd[1])[j]);
            float2 f2 = __half22float2(((const __half2*)&cd[2])[j]);
            float2 f3 = __half22float2(((const __half2*)&cd[3])[j]);
            float rx = gw[it][0]*f0.x + gw[it][1]*f1.x + gw[it][2]*f2.x + gw[it][3]*f3.x;
            float ry = gw[it][0]*f0.y + gw[it][1]*f1.y + gw[it][2]*f2.y + gw[it][3]*f3.y;
            __half2 h = __floats2half2_rn(rx, ry);
            po[j] = *(uint32_t*)&h;
        }
        *(uint4*)(dsmp + abuf_off + growl[it]*80 + (lid & 3)*16) = pk;
    };

    auto loadB = [&](int c, int p) {
        uint32_t sb = sbase + BBASE + p * BPL;
        size_t kOff = (size_t)c * KC;
        #pragma unroll
        for (int i = 0; i < 4; i++) {
            int idx = tid + i*256;
            int rr = idx >> 2;
            int j  = idx & 3;
            cpa16(sb + rr*80 + j*16, g_B + (size_t)rr*Kd + kOff + j*8);
        }
        asm volatile("cp.async.commit_group;");
    };

    calc_tap(0);
    {
        uint4 cd[4];
        gather(0, 0, cd); combine_sts(0, cd, 0);
        gather(1, 0, cd); combine_sts(1, cd, 0);
    }
    loadB(0, 0);
    loadB(1, 1);
    loadB(2, 2);

    for (int c = 0; c < NCH; c++) {
        if (c + 3 < NCH) {
            asm volatile("cp.async.wait_group 2;" ::: "memory");
        } else if (c + 2 < NCH) {
            asm volatile("cp.async.wait_group 1;" ::: "memory");
        } else {
            asm volatile("cp.async.wait_group 0;" ::: "memory");
        }
        __syncthreads();

        const int prep = (c + 1 < NCH);
        const int cn = c + 1;
        if (prep && ((cn & 7) == 0)) calc_tap(cn >> 3);
        const int c0n = (cn & 7) * 32;
        const uint32_t abuf_n = (uint32_t)((cn & 1) * APL);

        uint32_t sbB = sbase + BBASE + (c & 3) * BPL;
        uint32_t sbA = sbase + (c & 1) * APL;

        uint4 cd0[4], cd1[4];
        if (prep) gather(0, c0n, cd0);

        // kh = 0
        {
            uint32_t ah[4][4];
            #pragma unroll
            for (int mt = 0; mt < 4; mt++)
                LDMX4(ah[mt], sbA + a_off + mt*(16*80));
            #pragma unroll
            for (int tp = 0; tp < 4; tp++) {
                uint32_t bfr[4];
                LDMX4(bfr, sbB + bm_off + tp*(16*80));
                #pragma unroll
                for (int q = 0; q < 2; q++) {
                    int nt = tp*2 + q;
                    #pragma unroll
                    for (int mt = 0; mt < 4; mt++)
                        MMA16816(acc[mt][nt], ah[mt], bfr[2*q], bfr[2*q+1]);
                }
            }
        }
        if (prep) { combine_sts(0, cd0, abuf_n); gather(1, c0n, cd1); }
        // kh = 1
        {
            uint32_t ah[4][4];
            #pragma unroll
            for (int mt = 0; mt < 4; mt++)
                LDMX4(ah[mt], sbA + a_off + mt*(16*80) + 32);
            #pragma unroll
            for (int tp = 0; tp < 4; tp++) {
                uint32_t bfr[4];
                LDMX4(bfr, sbB + bm_off + tp*(16*80) + 32);
                #pragma unroll
                for (int q = 0; q < 2; q++) {
                    int nt = tp*2 + q;
                    #pragma unroll
                    for (int mt = 0; mt < 4; mt++)
                        MMA16816(acc[mt][nt], ah[mt], bfr[2*q], bfr[2*q+1]);
                }
            }
        }
        if (prep) combine_sts(1, cd1, abuf_n);
        if (c + 3 < NCH) loadB(c + 3, (c + 3) & 3);
    }

    #pragma unroll
    for (int mt = 0; mt < 4; mt++) {
        int mA = m0 + warpM*64 + mt*16 + (lid >> 2);
        int mB = mA + 8;
        int bA = mA >> 12, bB = mB >> 12;
        int pA = mA & 4095, pB = mB & 4095;
        #pragma unroll
        for (int nt = 0; nt < 8; nt++) {
            int o = warpN*64 + nt*8 + (lid & 3)*2;
            float bv0 = g_bias2[o], bv1 = g_bias2[o + 1];
            float* d = acc[mt][nt];
            out[((size_t)bA << 20) + ((size_t)o << 12)     + pA] = fmaxf(d[0] + bv0, 0.f);
            out[((size_t)bA << 20) + ((size_t)(o+1) << 12) + pA] = fmaxf(d[1] + bv1, 0.f);
            out[((size_t)bB << 20) + ((size_t)o << 12)     + pB] = fmaxf(d[2] + bv0, 0.f);
            out[((size_t)bB << 20) + ((size_t)(o+1) << 12) + pB] = fmaxf(d[3] + bv1, 0.f);
        }
    }
}

// ---------------- launch ----------------
extern "C" void kernel_launch(void* const* d_in, const int* in_sizes, int n_in,
                              void* d_out, int out_size) {
    const float* input  = (const float*)d_in[0];
    const float* w_off  = (const float*)d_in[1];
    const float* b_off  = (const float*)d_in[2];
    const float* weight = (const float*)d_in[3];
    const float* bias   = (const float*)d_in[4];
    const float* gamma  = (const float*)d_in[5];
    const float* beta   = (const float*)d_in[6];
    const float* mean   = (const float*)d_in[7];
    const float* var    = (const float*)d_in[8];
    float* out = (float*)d_out;

    cudaFuncSetAttribute(k_gemm_fused, cudaFuncAttributeMaxDynamicSharedMemorySize, SMEMSZ);
    cudaFuncSetAttribute(k_offset_gemm, cudaFuncAttributeMaxDynamicSharedMemorySize, NSTG2*STG2);

    k_transpose_prep<<<dim3(2, 10, 256), dim3(32, 8)>>>(input, weight, w_off, bias, gamma, beta, mean, var);
    k_offset_gemm<<<Md/128, 256, NSTG2*STG2>>>(b_off);
    k_gemm_fused<<<Md/128, 256, SMEMSZ>>>(out);
}